// round 14
// baseline (speedup 1.0000x reference)
#include <cuda_runtime.h>
#include <cuda_fp16.h>
#include <cstdint>

#define NN 100000
#define EE 1600000
#define FEADIM 128
#define HH 64
#define GG 512
#define NLAYERS 4
#define BN_EPS 1e-5f
#define SCAN_NBLK 98   // ceil((NN+1)/1024)
#define GEMM_BLOCKS ((NN + 127) / 128)   // 782

// ---------------- scratch (all activations fp16) ----------------
__device__ __half g_tA16[(size_t)NN * HH];
__device__ __half g_tB16[(size_t)NN * HH];
__device__ __half g_z16[(size_t)NN * HH];
__device__ __half g_h16[(size_t)NN * HH];
__device__ float  g_stats[10 * 128];
__device__ float  g_ab[10 * 128];
__device__ float  g_pooled[(NLAYERS + 1) * GG * HH];
__device__ int    g_cnt[GG];
__device__ int    g_deg[NN];
__device__ int    g_cur[NN];
__device__ int    g_off[NN + 1];
__device__ int    g_bsum[SCAN_NBLK];
__device__ int    g_csr[EE];
__device__ int    g_done[16];

__device__ __forceinline__ void red_add_v4(float* p, float4 v) {
    asm volatile("red.global.add.v4.f32 [%0], {%1,%2,%3,%4};"
                 :: "l"(p), "f"(v.x), "f"(v.y), "f"(v.z), "f"(v.w) : "memory");
}
__device__ __forceinline__ void mma_f16(float& c0, float& c1, float& c2, float& c3,
                                        uint32_t a0, uint32_t a1, uint32_t a2, uint32_t a3,
                                        uint32_t b0, uint32_t b1) {
    asm volatile("mma.sync.aligned.m16n8k16.row.col.f32.f16.f16.f32 "
                 "{%0,%1,%2,%3}, {%4,%5,%6,%7}, {%8,%9}, {%0,%1,%2,%3};"
                 : "+f"(c0), "+f"(c1), "+f"(c2), "+f"(c3)
                 : "r"(a0), "r"(a1), "r"(a2), "r"(a3), "r"(b0), "r"(b1));
}
__device__ __forceinline__ void h8_add(uint4 v, float* a) {
    float2 f;
    f = __half22float2(*(__half2*)&v.x); a[0] += f.x; a[1] += f.y;
    f = __half22float2(*(__half2*)&v.y); a[2] += f.x; a[3] += f.y;
    f = __half22float2(*(__half2*)&v.z); a[4] += f.x; a[5] += f.y;
    f = __half22float2(*(__half2*)&v.w); a[6] += f.x; a[7] += f.y;
}
__device__ __forceinline__ uint32_t trans_h2(uint32_t p, float a0, float o0, float a1, float o1) {
    float2 f = __half22float2(*(__half2*)&p);
    f.x = fmaxf(0.f, a0 * f.x + o0);
    f.y = fmaxf(0.f, a1 * f.y + o1);
    __half2 h = __floats2half2_rn(f.x, f.y);
    return *(uint32_t*)&h;
}

// ---------------- setup kernels ----------------

__global__ void zero_kernel() {
    const int TOT = (NLAYERS + 1) * GG * HH;
    for (int i = blockIdx.x * blockDim.x + threadIdx.x; i < TOT;
         i += gridDim.x * blockDim.x) {
        g_pooled[i] = 0.f;
        if (i < NN) { g_deg[i] = 0; g_cur[i] = 0; }
        if (i < 10 * 128) g_stats[i] = 0.f;
        if (i < GG) g_cnt[i] = 0;
        if (i < 16) g_done[i] = 0;
    }
}

__global__ void count_kernel(const int* __restrict__ edge, const int* __restrict__ batch) {
    int i = blockIdx.x * blockDim.x + threadIdx.x;
    if (i < EE) atomicAdd(&g_deg[edge[EE + i]], 1);
    if (i < NN) atomicAdd(&g_cnt[batch[i]], 1);
}

__global__ void scan_block_kernel() {
    __shared__ int s[1024];
    int tid = threadIdx.x;
    int i = blockIdx.x * 1024 + tid;
    int v = (i < NN) ? g_deg[i] : 0;
    s[tid] = v;
    __syncthreads();
    for (int off = 1; off < 1024; off <<= 1) {
        int t = (tid >= off) ? s[tid - off] : 0;
        __syncthreads();
        s[tid] += t;
        __syncthreads();
    }
    if (i <= NN) g_off[i] = s[tid] - v;
    if (tid == 1023) g_bsum[blockIdx.x] = s[1023];
}

__global__ void scan_add_kernel() {
    __shared__ int sb[128];
    int tid = threadIdx.x;
    if (tid < 128) sb[tid] = (tid < (int)blockIdx.x && tid < SCAN_NBLK) ? g_bsum[tid] : 0;
    __syncthreads();
    if (tid < 64) sb[tid] += sb[tid + 64];
    __syncthreads();
    if (tid < 32) {
        int v = sb[tid] + sb[tid + 32];
#pragma unroll
        for (int m = 16; m > 0; m >>= 1) v += __shfl_xor_sync(0xffffffffu, v, m);
        if (tid == 0) sb[0] = v;
    }
    __syncthreads();
    int base = sb[0];
    int i = blockIdx.x * 1024 + tid;
    if (i <= NN) g_off[i] += base;
}

__global__ void fill_csr_kernel(const int* __restrict__ edge) {
    int e = blockIdx.x * blockDim.x + threadIdx.x;
    if (e >= EE) return;
    int d = edge[EE + e];
    int pos = g_off[d] + atomicAdd(&g_cur[d], 1);
    g_csr[pos] = edge[e];
}

// ---------------- fp16 tensor-core GEMM + fused BN stats & finalize ----------------
// Y16[N,64] = f(A)[N,K] @ W[K,64] + bias; f optional relu(a*x+c) from g_ab[tstage].
// A tiles as fp16 [128][k32] (stride 40 halves); W transposed fp16 [64][k32] (stride 40).
// Asel: 0 = Aext fp32 (x), 1 = g_tA16, 2 = g_z16.  Ysel: 0 = g_tA16, 1 = g_tB16.
__global__ __launch_bounds__(256) void gemm_tc_kernel(
    const float* __restrict__ Aext, int Asel, int K,
    const float* __restrict__ W, const float* __restrict__ bias,
    int tstage, int Ysel, int sstage,
    const float* __restrict__ gamma, const float* __restrict__ beta)
{
    const __half* Ah = (Asel == 1) ? g_tA16 : g_z16;
    __half* Y = (Ysel == 0) ? g_tA16 : g_tB16;
    const float* trans = (tstage >= 0) ? (g_ab + tstage * 128) : nullptr;
    float* stats = g_stats + sstage * 128;

    __shared__ __half As_h[128 * 40];   // 10240 B, uint32 row stride 20
    __shared__ __half Ws_h[64 * 40];    // 5120 B, transposed [n][k]
    __shared__ float  sw[8 * 128];
    __shared__ bool   slast;
    const uint32_t* As_u = (const uint32_t*)As_h;
    const uint32_t* Ws_u = (const uint32_t*)Ws_h;

    int tid = threadIdx.x;
    int wid = tid >> 5, lane = tid & 31;
    int g = lane >> 2, tig = lane & 3;
    int row0 = blockIdx.x * 128;
    int wr0 = wid * 16;

    float c[8][4];
#pragma unroll
    for (int j = 0; j < 8; j++)
#pragma unroll
        for (int q = 0; q < 4; q++) c[j][q] = 0.f;

    const int nchunk = K >> 5;
    for (int ch = 0; ch < nchunk; ch++) {
        int k0 = ch * 32;
        // ---- load A chunk (full 128 x 32 halves) ----
        if (Asel == 0) {
            // fp32 input: 128 rows x 8 float4 (32 floats) -> half
#pragma unroll
            for (int i = 0; i < 4; i++) {
                int li = tid + i * 256;
                int r = li >> 3, cq = li & 7;
                int grow = row0 + r;
                float4 v = make_float4(0.f, 0.f, 0.f, 0.f);
                if (grow < NN) v = *(const float4*)(Aext + (size_t)grow * K + k0 + cq * 4);
                __half2 h0 = __floats2half2_rn(v.x, v.y);
                __half2 h1 = __floats2half2_rn(v.z, v.w);
                uint2 pk;
                pk.x = *(uint32_t*)&h0; pk.y = *(uint32_t*)&h1;
                *(uint2*)(&As_h[r * 40 + cq * 4]) = pk;
            }
        } else {
            // fp16 input: 128 rows x 4 uint4 (8 halves each) = 32 halves/row
#pragma unroll
            for (int i = 0; i < 2; i++) {
                int li = tid + i * 256;
                int r = li >> 2, cq = li & 3;
                int grow = row0 + r;
                uint4 p = make_uint4(0u, 0u, 0u, 0u);
                if (grow < NN) p = *(const uint4*)(Ah + (size_t)grow * 64 + k0 + cq * 8);
                if (trans) {
                    int kb = k0 + cq * 8;
                    p.x = trans_h2(p.x, trans[kb + 0], trans[64 + kb + 0],
                                        trans[kb + 1], trans[64 + kb + 1]);
                    p.y = trans_h2(p.y, trans[kb + 2], trans[64 + kb + 2],
                                        trans[kb + 3], trans[64 + kb + 3]);
                    p.z = trans_h2(p.z, trans[kb + 4], trans[64 + kb + 4],
                                        trans[kb + 5], trans[64 + kb + 5]);
                    p.w = trans_h2(p.w, trans[kb + 6], trans[64 + kb + 6],
                                        trans[kb + 7], trans[64 + kb + 7]);
                }
                *(uint4*)(&As_h[r * 40 + cq * 8]) = p;
            }
        }
        // ---- load W chunk, transposed: Ws[n][k] = W[k0+k][n] ----
#pragma unroll
        for (int i = 0; i < 2; i++) {
            int li = tid + i * 256;
            int kr = li >> 4, n4 = li & 15;
            float4 w = *(const float4*)(W + (size_t)(k0 + kr) * 64 + n4 * 4);
            Ws_h[(n4 * 4 + 0) * 40 + kr] = __float2half(w.x);
            Ws_h[(n4 * 4 + 1) * 40 + kr] = __float2half(w.y);
            Ws_h[(n4 * 4 + 2) * 40 + kr] = __float2half(w.z);
            Ws_h[(n4 * 4 + 3) * 40 + kr] = __float2half(w.w);
        }
        __syncthreads();
        // ---- MMA: 2 k16 steps per chunk ----
#pragma unroll
        for (int s = 0; s < 2; s++) {
            int kb = s * 8;   // uint32 offset within row (16 halves)
            uint32_t a0 = As_u[(wr0 + g) * 20 + kb + tig];
            uint32_t a1 = As_u[(wr0 + g + 8) * 20 + kb + tig];
            uint32_t a2 = As_u[(wr0 + g) * 20 + kb + 4 + tig];
            uint32_t a3 = As_u[(wr0 + g + 8) * 20 + kb + 4 + tig];
#pragma unroll
            for (int j = 0; j < 8; j++) {
                int n = j * 8 + g;
                uint32_t b0 = Ws_u[n * 20 + kb + tig];
                uint32_t b1 = Ws_u[n * 20 + kb + 4 + tig];
                mma_f16(c[j][0], c[j][1], c[j][2], c[j][3], a0, a1, a2, a3, b0, b1);
            }
        }
        __syncthreads();
    }

    // ---- epilogue: bias, fp16 store, BN stats ----
    int rlo = row0 + wr0 + g;
    int rhi = rlo + 8;
    bool vlo = rlo < NN, vhi = rhi < NN;
#pragma unroll
    for (int j = 0; j < 8; j++) {
        int e0 = j * 8 + 2 * tig;
        float b0 = bias[e0], b1 = bias[e0 + 1];
        float y00 = c[j][0] + b0, y01 = c[j][1] + b1;
        float y10 = c[j][2] + b0, y11 = c[j][3] + b1;
        if (vlo) *(__half2*)(Y + (size_t)rlo * 64 + e0) = __floats2half2_rn(y00, y01);
        if (vhi) *(__half2*)(Y + (size_t)rhi * 64 + e0) = __floats2half2_rn(y10, y11);
        float s0 = (vlo ? y00 : 0.f) + (vhi ? y10 : 0.f);
        float s1 = (vlo ? y01 : 0.f) + (vhi ? y11 : 0.f);
        float q0 = (vlo ? y00 * y00 : 0.f) + (vhi ? y10 * y10 : 0.f);
        float q1 = (vlo ? y01 * y01 : 0.f) + (vhi ? y11 * y11 : 0.f);
#pragma unroll
        for (int m = 4; m <= 16; m <<= 1) {
            s0 += __shfl_xor_sync(0xffffffffu, s0, m);
            s1 += __shfl_xor_sync(0xffffffffu, s1, m);
            q0 += __shfl_xor_sync(0xffffffffu, q0, m);
            q1 += __shfl_xor_sync(0xffffffffu, q1, m);
        }
        if (g == 0) {
            sw[wid * 128 + e0] = s0;
            sw[wid * 128 + e0 + 1] = s1;
            sw[wid * 128 + 64 + e0] = q0;
            sw[wid * 128 + 64 + e0 + 1] = q1;
        }
    }
    __syncthreads();
    if (tid < 128) {
        float tot = 0.f;
#pragma unroll
        for (int w = 0; w < 8; w++) tot += sw[w * 128 + tid];
        atomicAdd(&stats[tid], tot);
        __threadfence();
    }
    __syncthreads();
    if (tid == 0) {
        int v = atomicAdd(&g_done[sstage], 1);
        slast = (v == (int)gridDim.x - 1);
    }
    __syncthreads();
    if (slast && tid < 64) {
        float s_ = __ldcg(&stats[tid]);
        float q_ = __ldcg(&stats[64 + tid]);
        float m = s_ * (1.f / NN);
        float var = q_ * (1.f / NN) - m * m;
        float a = gamma[tid] * rsqrtf(var + BN_EPS);
        g_ab[sstage * 128 + tid] = a;
        g_ab[sstage * 128 + 64 + tid] = beta[tid] - a * m;
    }
}

// ---------------- activate + pool (+ optional fp16 h write) ----------------
__global__ __launch_bounds__(256) void act_pool_kernel(int sstage, int level,
                                                       const int* __restrict__ batch,
                                                       int write_h)
{
    __shared__ float4 su[16][17];
    __shared__ int sb[16];
    const float* ab = g_ab + sstage * 128;
    float* pooled_level = g_pooled + (size_t)level * GG * HH;
    int tid = threadIdx.x;
    int rl = tid >> 4, qq = tid & 15;
    int r = blockIdx.x * 16 + rl;           // NN = 6250*16, always valid
    int cc = qq * 4;

    uint2 p = ((const uint2*)g_tB16)[(size_t)r * 16 + qq];
    float2 f0 = __half22float2(*(__half2*)&p.x);
    float2 f1 = __half22float2(*(__half2*)&p.y);
    float4 u;
    u.x = fmaxf(0.f, ab[cc + 0] * f0.x + ab[64 + cc + 0]);
    u.y = fmaxf(0.f, ab[cc + 1] * f0.y + ab[64 + cc + 1]);
    u.z = fmaxf(0.f, ab[cc + 2] * f1.x + ab[64 + cc + 2]);
    u.w = fmaxf(0.f, ab[cc + 3] * f1.y + ab[64 + cc + 3]);
    int b = batch[r];

    if (write_h) {
        __half2 p0 = __floats2half2_rn(u.x, u.y);
        __half2 p1 = __floats2half2_rn(u.z, u.w);
        uint2 pk;
        pk.x = *(uint32_t*)&p0;
        pk.y = *(uint32_t*)&p1;
        ((uint2*)g_h16)[(size_t)r * 16 + qq] = pk;
    }

    if (qq == 0) sb[rl] = b;
    su[rl][qq] = u;
    __syncthreads();
    bool head = (rl == 0) || (b != sb[rl - 1]);
    if (head) {
        float4 acc = u;
        for (int k = rl + 1; k < 16 && sb[k] == b; k++) {
            float4 w = su[k][qq];
            acc.x += w.x; acc.y += w.y; acc.z += w.z; acc.w += w.w;
        }
        red_add_v4(pooled_level + (size_t)b * 64 + cc, acc);
    }
}

// ---------------- fp16 CSR gather: z16[i] = h[i] + sum_{j->i} h[j] ----------------
__global__ __launch_bounds__(256) void gather_kernel() {
    int gt = blockIdx.x * 256 + threadIdx.x;
    int node = gt >> 3;                   // grid sized exactly: NN*8/256
    int l8 = threadIdx.x & 7;

    int off0 = g_off[node];
    int cnt = g_off[node + 1] - off0;

    const uint4* hr = (const uint4*)g_h16;
    float acc[8];
#pragma unroll
    for (int i = 0; i < 8; i++) acc[i] = 0.f;
    h8_add(hr[(size_t)node * 8 + l8], acc);

    int vmax = cnt;
#pragma unroll
    for (int sft = 16; sft > 0; sft >>= 1)
        vmax = max(vmax, __shfl_xor_sync(0xffffffffu, vmax, sft));

    for (int base = 0; base < vmax; base += 8) {
        int myidx = (base + l8 < cnt) ? g_csr[off0 + base + l8] : -1;
#pragma unroll
        for (int j = 0; j < 8; j++) {
            int idx = __shfl_sync(0xffffffffu, myidx, j, 8);
            if (idx >= 0) h8_add(hr[(size_t)idx * 8 + l8], acc);
        }
    }
    __half2 o0 = __floats2half2_rn(acc[0], acc[1]);
    __half2 o1 = __floats2half2_rn(acc[2], acc[3]);
    __half2 o2 = __floats2half2_rn(acc[4], acc[5]);
    __half2 o3 = __floats2half2_rn(acc[6], acc[7]);
    uint4 pk;
    pk.x = *(uint32_t*)&o0; pk.y = *(uint32_t*)&o1;
    pk.z = *(uint32_t*)&o2; pk.w = *(uint32_t*)&o3;
    ((uint4*)g_z16)[(size_t)node * 8 + l8] = pk;
}

// ---------------- readout ----------------
__global__ void final_kernel(const float* __restrict__ linW,
                             const float* __restrict__ linb,
                             float* __restrict__ out)
{
    __shared__ float ps[(NLAYERS + 1) * 64];
    int g = blockIdx.x, t = threadIdx.x;
    for (int i = t; i < (NLAYERS + 1) * 64; i += 64) {
        int l = i >> 6, j = i & 63;
        ps[i] = g_pooled[(size_t)l * GG * 64 + (size_t)g * 64 + j];
    }
    __syncthreads();
    float acc = (float)g_cnt[g] * linb[t];
#pragma unroll
    for (int l = 1; l < NLAYERS + 1; l++) acc += linb[l * 64 + t];
    for (int l = 0; l < NLAYERS + 1; l++) {
        const float* wl = linW + (size_t)l * 64 * 64;
#pragma unroll 8
        for (int j = 0; j < 64; j++)
            acc += ps[l * 64 + j] * wl[j * 64 + t];
    }
    out[(size_t)g * 64 + t] = acc;
}

// ---------------- launch ----------------

extern "C" void kernel_launch(void* const* d_in, const int* in_sizes, int n_in,
                              void* d_out, int out_size)
{
    const float* x     = (const float*)d_in[0];
    const int*   edge  = (const int*)d_in[1];
    const int*   batch = (const int*)d_in[2];
    const float* fW1 = (const float*)d_in[3];
    const float* fb1 = (const float*)d_in[4];
    const float* fg1 = (const float*)d_in[5];
    const float* fbt1= (const float*)d_in[6];
    const float* fW2 = (const float*)d_in[7];
    const float* fb2 = (const float*)d_in[8];
    const float* fg2 = (const float*)d_in[9];
    const float* fbt2= (const float*)d_in[10];
    const float* cW1 = (const float*)d_in[11];
    const float* cb1 = (const float*)d_in[12];
    const float* cg1 = (const float*)d_in[13];
    const float* cbt1= (const float*)d_in[14];
    const float* cW2 = (const float*)d_in[15];
    const float* cb2 = (const float*)d_in[16];
    const float* cg2 = (const float*)d_in[17];
    const float* cbt2= (const float*)d_in[18];
    const float* linW= (const float*)d_in[19];
    const float* linb= (const float*)d_in[20];

    const int ap_blocks  = NN / 16;       // 6250 (exact)
    const int gat_blocks = NN * 8 / 256;  // 3125 (exact)

    zero_kernel<<<640, 256>>>();
    count_kernel<<<(EE + 255) / 256, 256>>>(edge, batch);
    scan_block_kernel<<<SCAN_NBLK, 1024>>>();
    scan_add_kernel<<<SCAN_NBLK, 1024>>>();
    fill_csr_kernel<<<(EE + 255) / 256, 256>>>(edge);

    // first_h: x(fp32) -> tA16 ; relu(ab0∘tA16) -> tB16
    gemm_tc_kernel<<<GEMM_BLOCKS, 256>>>(x, 0, FEADIM, fW1, fb1, -1, 0, 0, fg1, fbt1);
    gemm_tc_kernel<<<GEMM_BLOCKS, 256>>>(nullptr, 1, HH, fW2, fb2, 0, 1, 1, fg2, fbt2);

    for (int l = 0; l < NLAYERS; l++) {
        int sA = 2 + 2 * l, sB = 3 + 2 * l;
        act_pool_kernel<<<ap_blocks, 256>>>(2 * l + 1, l, batch, 1);
        gather_kernel<<<gat_blocks, 256>>>();
        gemm_tc_kernel<<<GEMM_BLOCKS, 256>>>(nullptr, 2, HH,
                                             cW1 + (size_t)l * HH * HH, cb1 + (size_t)l * HH,
                                             -1, 0, sA, cg1 + (size_t)l * HH, cbt1 + (size_t)l * HH);
        gemm_tc_kernel<<<GEMM_BLOCKS, 256>>>(nullptr, 1, HH,
                                             cW2 + (size_t)l * HH * HH, cb2 + (size_t)l * HH,
                                             sA, 1, sB, cg2 + (size_t)l * HH, cbt2 + (size_t)l * HH);
    }
    act_pool_kernel<<<ap_blocks, 256>>>(9, NLAYERS, batch, 0);
    final_kernel<<<GG, 64>>>(linW, linb, (float*)d_out);
}

// round 15
// speedup vs baseline: 1.0533x; 1.0533x over previous
#include <cuda_runtime.h>
#include <cuda_fp16.h>
#include <cstdint>

#define NN 100000
#define EE 1600000
#define FEADIM 128
#define HH 64
#define GG 512
#define NLAYERS 4
#define BN_EPS 1e-5f
#define SCAN_NBLK 98   // ceil((NN+1)/1024)
#define GEMM_BLOCKS ((NN + 127) / 128)   // 782

// ---------------- scratch (all activations fp16; 10-bit mantissa == tf32) ----------------
__device__ __half g_tA16[(size_t)NN * HH];
__device__ __half g_tB16[(size_t)NN * HH];
__device__ __half g_z16[(size_t)NN * HH];
__device__ __half g_h16[(size_t)NN * HH];
__device__ float  g_stats[10 * 128];
__device__ float  g_ab[10 * 128];
__device__ float  g_pooled[(NLAYERS + 1) * GG * HH];
__device__ int    g_cnt[GG];
__device__ int    g_deg[NN];
__device__ int    g_cur[NN];
__device__ int    g_off[NN + 1];
__device__ int    g_bsum[SCAN_NBLK];
__device__ int    g_csr[EE];
__device__ int    g_done[16];

__device__ __forceinline__ void red_add_v4(float* p, float4 v) {
    asm volatile("red.global.add.v4.f32 [%0], {%1,%2,%3,%4};"
                 :: "l"(p), "f"(v.x), "f"(v.y), "f"(v.z), "f"(v.w) : "memory");
}
__device__ __forceinline__ uint32_t f2tf32(float f) {
    uint32_t r;
    asm("cvt.rna.tf32.f32 %0, %1;" : "=r"(r) : "f"(f));
    return r;
}
__device__ __forceinline__ void mma_tf32(float& c0, float& c1, float& c2, float& c3,
                                         uint32_t a0, uint32_t a1, uint32_t a2, uint32_t a3,
                                         uint32_t b0, uint32_t b1) {
    asm volatile("mma.sync.aligned.m16n8k8.row.col.f32.tf32.tf32.f32 "
                 "{%0,%1,%2,%3}, {%4,%5,%6,%7}, {%8,%9}, {%0,%1,%2,%3};"
                 : "+f"(c0), "+f"(c1), "+f"(c2), "+f"(c3)
                 : "r"(a0), "r"(a1), "r"(a2), "r"(a3), "r"(b0), "r"(b1));
}
__device__ __forceinline__ void h8_add(uint4 v, float* a) {
    float2 f;
    f = __half22float2(*(__half2*)&v.x); a[0] += f.x; a[1] += f.y;
    f = __half22float2(*(__half2*)&v.y); a[2] += f.x; a[3] += f.y;
    f = __half22float2(*(__half2*)&v.z); a[4] += f.x; a[5] += f.y;
    f = __half22float2(*(__half2*)&v.w); a[6] += f.x; a[7] += f.y;
}

// ---------------- setup kernels ----------------

__global__ void zero_kernel() {
    const int TOT = (NLAYERS + 1) * GG * HH;
    for (int i = blockIdx.x * blockDim.x + threadIdx.x; i < TOT;
         i += gridDim.x * blockDim.x) {
        g_pooled[i] = 0.f;
        if (i < NN) { g_deg[i] = 0; g_cur[i] = 0; }
        if (i < 10 * 128) g_stats[i] = 0.f;
        if (i < GG) g_cnt[i] = 0;
        if (i < 16) g_done[i] = 0;
    }
}

__global__ void count_kernel(const int* __restrict__ edge, const int* __restrict__ batch) {
    int i = blockIdx.x * blockDim.x + threadIdx.x;
    if (i < EE) atomicAdd(&g_deg[edge[EE + i]], 1);
    if (i < NN) atomicAdd(&g_cnt[batch[i]], 1);
}

__global__ void scan_block_kernel() {
    __shared__ int s[1024];
    int tid = threadIdx.x;
    int i = blockIdx.x * 1024 + tid;
    int v = (i < NN) ? g_deg[i] : 0;
    s[tid] = v;
    __syncthreads();
    for (int off = 1; off < 1024; off <<= 1) {
        int t = (tid >= off) ? s[tid - off] : 0;
        __syncthreads();
        s[tid] += t;
        __syncthreads();
    }
    if (i <= NN) g_off[i] = s[tid] - v;
    if (tid == 1023) g_bsum[blockIdx.x] = s[1023];
}

__global__ void scan_add_kernel() {
    __shared__ int sb[128];
    int tid = threadIdx.x;
    if (tid < 128) sb[tid] = (tid < (int)blockIdx.x && tid < SCAN_NBLK) ? g_bsum[tid] : 0;
    __syncthreads();
    if (tid < 64) sb[tid] += sb[tid + 64];
    __syncthreads();
    if (tid < 32) {
        int v = sb[tid] + sb[tid + 32];
#pragma unroll
        for (int m = 16; m > 0; m >>= 1) v += __shfl_xor_sync(0xffffffffu, v, m);
        if (tid == 0) sb[0] = v;
    }
    __syncthreads();
    int base = sb[0];
    int i = blockIdx.x * 1024 + tid;
    if (i <= NN) g_off[i] += base;
}

__global__ void fill_csr_kernel(const int* __restrict__ edge) {
    int e = blockIdx.x * blockDim.x + threadIdx.x;
    if (e >= EE) return;
    int d = edge[EE + e];
    int pos = g_off[d] + atomicAdd(&g_cur[d], 1);
    g_csr[pos] = edge[e];
}

// ---------------- tf32 GEMM (fp16 in/out for internal stages) + fused BN ----------------
// Asel: 0 = Aext fp32 (x), 1 = g_tA16, 2 = g_z16.  Ysel: 0 = g_tA16, 1 = g_tB16.
__global__ __launch_bounds__(256) void gemm_tc_kernel(
    const float* __restrict__ Aext, int Asel, int K,
    const float* __restrict__ W, const float* __restrict__ bias,
    int tstage, int Ysel, int sstage,
    const float* __restrict__ gamma, const float* __restrict__ beta)
{
    const __half* Ah = (Asel == 1) ? g_tA16 : g_z16;
    __half* Y = (Ysel == 0) ? g_tA16 : g_tB16;
    const float* trans = (tstage >= 0) ? (g_ab + tstage * 128) : nullptr;
    float* stats = g_stats + sstage * 128;

    __shared__ uint32_t As_u[128 * 36];
    __shared__ uint32_t Bs_u[32 * 72];
    __shared__ float    sw[8 * 128];
    __shared__ bool     slast;

    int tid = threadIdx.x;
    int wid = tid >> 5, lane = tid & 31;
    int g = lane >> 2, tig = lane & 3;
    int row0 = blockIdx.x * 128;
    int wr0 = wid * 16;

    float c[8][4];
#pragma unroll
    for (int j = 0; j < 8; j++)
#pragma unroll
        for (int q = 0; q < 4; q++) c[j][q] = 0.f;

    const int nchunk = K >> 5;
    for (int ch = 0; ch < nchunk; ch++) {
        int k0 = ch * 32;
#pragma unroll
        for (int i = 0; i < 4; i++) {
            int li = tid + i * 256;
            int r = li >> 3, c4 = li & 7;
            int grow = row0 + r;
            float4 v = make_float4(0.f, 0.f, 0.f, 0.f);
            if (grow < NN) {
                if (Asel == 0) {
                    v = *(const float4*)(Aext + (size_t)grow * K + k0 + c4 * 4);
                } else {
                    uint2 p = *(const uint2*)(Ah + (size_t)grow * 64 + k0 + c4 * 4);
                    float2 f0 = __half22float2(*(__half2*)&p.x);
                    float2 f1 = __half22float2(*(__half2*)&p.y);
                    v = make_float4(f0.x, f0.y, f1.x, f1.y);
                }
            }
            if (trans) {
                int kb = k0 + c4 * 4;
                v.x = fmaxf(0.f, trans[kb + 0] * v.x + trans[64 + kb + 0]);
                v.y = fmaxf(0.f, trans[kb + 1] * v.y + trans[64 + kb + 1]);
                v.z = fmaxf(0.f, trans[kb + 2] * v.z + trans[64 + kb + 2]);
                v.w = fmaxf(0.f, trans[kb + 3] * v.w + trans[64 + kb + 3]);
            }
            uint4 u;
            u.x = f2tf32(v.x); u.y = f2tf32(v.y); u.z = f2tf32(v.z); u.w = f2tf32(v.w);
            *(uint4*)(&As_u[r * 36 + c4 * 4]) = u;
        }
#pragma unroll
        for (int i = 0; i < 2; i++) {
            int li = tid + i * 256;
            int kr = li >> 4, n4 = li & 15;
            float4 w = *(const float4*)(W + (size_t)(k0 + kr) * 64 + n4 * 4);
            uint4 u;
            u.x = f2tf32(w.x); u.y = f2tf32(w.y); u.z = f2tf32(w.z); u.w = f2tf32(w.w);
            *(uint4*)(&Bs_u[kr * 72 + n4 * 4]) = u;
        }
        __syncthreads();
#pragma unroll
        for (int s = 0; s < 4; s++) {
            int k8 = s * 8;
            uint32_t a0 = As_u[(wr0 + g) * 36 + k8 + tig];
            uint32_t a1 = As_u[(wr0 + g + 8) * 36 + k8 + tig];
            uint32_t a2 = As_u[(wr0 + g) * 36 + k8 + tig + 4];
            uint32_t a3 = As_u[(wr0 + g + 8) * 36 + k8 + tig + 4];
#pragma unroll
            for (int j = 0; j < 8; j++) {
                uint32_t b0 = Bs_u[(k8 + tig) * 72 + j * 8 + g];
                uint32_t b1 = Bs_u[(k8 + tig + 4) * 72 + j * 8 + g];
                mma_tf32(c[j][0], c[j][1], c[j][2], c[j][3], a0, a1, a2, a3, b0, b1);
            }
        }
        __syncthreads();
    }

    int rlo = row0 + wr0 + g;
    int rhi = rlo + 8;
    bool vlo = rlo < NN, vhi = rhi < NN;
#pragma unroll
    for (int j = 0; j < 8; j++) {
        int e0 = j * 8 + 2 * tig;
        float b0 = bias[e0], b1 = bias[e0 + 1];
        float y00 = c[j][0] + b0, y01 = c[j][1] + b1;
        float y10 = c[j][2] + b0, y11 = c[j][3] + b1;
        if (vlo) *(__half2*)(Y + (size_t)rlo * 64 + e0) = __floats2half2_rn(y00, y01);
        if (vhi) *(__half2*)(Y + (size_t)rhi * 64 + e0) = __floats2half2_rn(y10, y11);
        float s0 = (vlo ? y00 : 0.f) + (vhi ? y10 : 0.f);
        float s1 = (vlo ? y01 : 0.f) + (vhi ? y11 : 0.f);
        float q0 = (vlo ? y00 * y00 : 0.f) + (vhi ? y10 * y10 : 0.f);
        float q1 = (vlo ? y01 * y01 : 0.f) + (vhi ? y11 * y11 : 0.f);
#pragma unroll
        for (int m = 4; m <= 16; m <<= 1) {
            s0 += __shfl_xor_sync(0xffffffffu, s0, m);
            s1 += __shfl_xor_sync(0xffffffffu, s1, m);
            q0 += __shfl_xor_sync(0xffffffffu, q0, m);
            q1 += __shfl_xor_sync(0xffffffffu, q1, m);
        }
        if (g == 0) {
            sw[wid * 128 + e0] = s0;
            sw[wid * 128 + e0 + 1] = s1;
            sw[wid * 128 + 64 + e0] = q0;
            sw[wid * 128 + 64 + e0 + 1] = q1;
        }
    }
    __syncthreads();
    if (tid < 128) {
        float tot = 0.f;
#pragma unroll
        for (int w = 0; w < 8; w++) tot += sw[w * 128 + tid];
        atomicAdd(&stats[tid], tot);
        __threadfence();
    }
    __syncthreads();
    if (tid == 0) {
        int v = atomicAdd(&g_done[sstage], 1);
        slast = (v == (int)gridDim.x - 1);
    }
    __syncthreads();
    if (slast && tid < 64) {
        float s_ = __ldcg(&stats[tid]);
        float q_ = __ldcg(&stats[64 + tid]);
        float m = s_ * (1.f / NN);
        float var = q_ * (1.f / NN) - m * m;
        float a = gamma[tid] * rsqrtf(var + BN_EPS);
        g_ab[sstage * 128 + tid] = a;
        g_ab[sstage * 128 + 64 + tid] = beta[tid] - a * m;
    }
}

// ---------------- activate + pool (+ optional fp16 h write) ----------------
__global__ __launch_bounds__(256) void act_pool_kernel(int sstage, int level,
                                                       const int* __restrict__ batch,
                                                       int write_h)
{
    __shared__ float4 su[16][17];
    __shared__ int sb[16];
    const float* ab = g_ab + sstage * 128;
    float* pooled_level = g_pooled + (size_t)level * GG * HH;
    int tid = threadIdx.x;
    int rl = tid >> 4, qq = tid & 15;
    int r = blockIdx.x * 16 + rl;           // NN = 6250*16, always valid
    int cc = qq * 4;

    uint2 p = ((const uint2*)g_tB16)[(size_t)r * 16 + qq];
    float2 f0 = __half22float2(*(__half2*)&p.x);
    float2 f1 = __half22float2(*(__half2*)&p.y);
    float4 u;
    u.x = fmaxf(0.f, ab[cc + 0] * f0.x + ab[64 + cc + 0]);
    u.y = fmaxf(0.f, ab[cc + 1] * f0.y + ab[64 + cc + 1]);
    u.z = fmaxf(0.f, ab[cc + 2] * f1.x + ab[64 + cc + 2]);
    u.w = fmaxf(0.f, ab[cc + 3] * f1.y + ab[64 + cc + 3]);
    int b = batch[r];

    if (write_h) {
        __half2 p0 = __floats2half2_rn(u.x, u.y);
        __half2 p1 = __floats2half2_rn(u.z, u.w);
        uint2 pk;
        pk.x = *(uint32_t*)&p0;
        pk.y = *(uint32_t*)&p1;
        ((uint2*)g_h16)[(size_t)r * 16 + qq] = pk;
    }

    if (qq == 0) sb[rl] = b;
    su[rl][qq] = u;
    __syncthreads();
    bool head = (rl == 0) || (b != sb[rl - 1]);
    if (head) {
        float4 acc = u;
        for (int k = rl + 1; k < 16 && sb[k] == b; k++) {
            float4 w = su[k][qq];
            acc.x += w.x; acc.y += w.y; acc.z += w.z; acc.w += w.w;
        }
        red_add_v4(pooled_level + (size_t)b * 64 + cc, acc);
    }
}

// ---------------- fp16 CSR gather: z16[i] = h[i] + sum_{j->i} h[j] ----------------
// 8 lanes per node; each lane covers 8 columns (one uint4 = 8 halves per row).
__global__ __launch_bounds__(256) void gather_kernel() {
    int gt = blockIdx.x * 256 + threadIdx.x;
    int node = gt >> 3;                   // grid sized exactly: NN*8/256
    int l8 = threadIdx.x & 7;

    int off0 = g_off[node];
    int cnt = g_off[node + 1] - off0;

    const uint4* hr = (const uint4*)g_h16;
    float acc[8];
#pragma unroll
    for (int i = 0; i < 8; i++) acc[i] = 0.f;
    h8_add(hr[(size_t)node * 8 + l8], acc);

    // warp-uniform bound so width-8 shuffles never diverge across subgroups
    int vmax = cnt;
#pragma unroll
    for (int sft = 16; sft > 0; sft >>= 1)
        vmax = max(vmax, __shfl_xor_sync(0xffffffffu, vmax, sft));

    for (int base = 0; base < vmax; base += 8) {
        int myidx = (base + l8 < cnt) ? g_csr[off0 + base + l8] : -1;
#pragma unroll
        for (int j = 0; j < 8; j++) {
            int idx = __shfl_sync(0xffffffffu, myidx, j, 8);
            if (idx >= 0) h8_add(hr[(size_t)idx * 8 + l8], acc);
        }
    }
    __half2 o0 = __floats2half2_rn(acc[0], acc[1]);
    __half2 o1 = __floats2half2_rn(acc[2], acc[3]);
    __half2 o2 = __floats2half2_rn(acc[4], acc[5]);
    __half2 o3 = __floats2half2_rn(acc[6], acc[7]);
    uint4 pk;
    pk.x = *(uint32_t*)&o0; pk.y = *(uint32_t*)&o1;
    pk.z = *(uint32_t*)&o2; pk.w = *(uint32_t*)&o3;
    ((uint4*)g_z16)[(size_t)node * 8 + l8] = pk;
}

// ---------------- readout ----------------
__global__ void final_kernel(const float* __restrict__ linW,
                             const float* __restrict__ linb,
                             float* __restrict__ out)
{
    __shared__ float ps[(NLAYERS + 1) * 64];
    int g = blockIdx.x, t = threadIdx.x;
    for (int i = t; i < (NLAYERS + 1) * 64; i += 64) {
        int l = i >> 6, j = i & 63;
        ps[i] = g_pooled[(size_t)l * GG * 64 + (size_t)g * 64 + j];
    }
    __syncthreads();
    float acc = (float)g_cnt[g] * linb[t];
#pragma unroll
    for (int l = 1; l < NLAYERS + 1; l++) acc += linb[l * 64 + t];
    for (int l = 0; l < NLAYERS + 1; l++) {
        const float* wl = linW + (size_t)l * 64 * 64;
#pragma unroll 8
        for (int j = 0; j < 64; j++)
            acc += ps[l * 64 + j] * wl[j * 64 + t];
    }
    out[(size_t)g * 64 + t] = acc;
}

// ---------------- launch ----------------

extern "C" void kernel_launch(void* const* d_in, const int* in_sizes, int n_in,
                              void* d_out, int out_size)
{
    const float* x     = (const float*)d_in[0];
    const int*   edge  = (const int*)d_in[1];
    const int*   batch = (const int*)d_in[2];
    const float* fW1 = (const float*)d_in[3];
    const float* fb1 = (const float*)d_in[4];
    const float* fg1 = (const float*)d_in[5];
    const float* fbt1= (const float*)d_in[6];
    const float* fW2 = (const float*)d_in[7];
    const float* fb2 = (const float*)d_in[8];
    const float* fg2 = (const float*)d_in[9];
    const float* fbt2= (const float*)d_in[10];
    const float* cW1 = (const float*)d_in[11];
    const float* cb1 = (const float*)d_in[12];
    const float* cg1 = (const float*)d_in[13];
    const float* cbt1= (const float*)d_in[14];
    const float* cW2 = (const float*)d_in[15];
    const float* cb2 = (const float*)d_in[16];
    const float* cg2 = (const float*)d_in[17];
    const float* cbt2= (const float*)d_in[18];
    const float* linW= (const float*)d_in[19];
    const float* linb= (const float*)d_in[20];

    const int ap_blocks  = NN / 16;       // 6250 (exact)
    const int gat_blocks = NN * 8 / 256;  // 3125 (exact)

    zero_kernel<<<640, 256>>>();
    count_kernel<<<(EE + 255) / 256, 256>>>(edge, batch);
    scan_block_kernel<<<SCAN_NBLK, 1024>>>();
    scan_add_kernel<<<SCAN_NBLK, 1024>>>();
    fill_csr_kernel<<<(EE + 255) / 256, 256>>>(edge);

    // first_h: x(fp32) -> tA16 ; relu(ab0∘tA16) -> tB16
    gemm_tc_kernel<<<GEMM_BLOCKS, 256>>>(x, 0, FEADIM, fW1, fb1, -1, 0, 0, fg1, fbt1);
    gemm_tc_kernel<<<GEMM_BLOCKS, 256>>>(nullptr, 1, HH, fW2, fb2, 0, 1, 1, fg2, fbt2);

    for (int l = 0; l < NLAYERS; l++) {
        int sA = 2 + 2 * l, sB = 3 + 2 * l;
        act_pool_kernel<<<ap_blocks, 256>>>(2 * l + 1, l, batch, 1);
        gather_kernel<<<gat_blocks, 256>>>();
        gemm_tc_kernel<<<GEMM_BLOCKS, 256>>>(nullptr, 2, HH,
                                             cW1 + (size_t)l * HH * HH, cb1 + (size_t)l * HH,
                                             -1, 0, sA, cg1 + (size_t)l * HH, cbt1 + (size_t)l * HH);
        gemm_tc_kernel<<<GEMM_BLOCKS, 256>>>(nullptr, 1, HH,
                                             cW2 + (size_t)l * HH * HH, cb2 + (size_t)l * HH,
                                             sA, 1, sB, cg2 + (size_t)l * HH, cbt2 + (size_t)l * HH);
    }
    act_pool_kernel<<<ap_blocks, 256>>>(9, NLAYERS, batch, 0);
    final_kernel<<<GG, 64>>>(linW, linb, (float*)d_out);
}